// round 16
// baseline (speedup 1.0000x reference)
#include <cuda_runtime.h>
#include <cstdint>

#define NPTS    65536
#define NQ      1024
#define NBATCH  2
#define NS1     32
#define NS2     64
#define NOUT    128
#define NSLAB   4
#define SLABPTS 16384               // points per index slab
#define NW      (SLABPTS / 32)      // 512 mask words per slab
#define NCELL   1000                // 10x10x10 cells
#define RP      0.201f              // r2 + margin for y/z cell boxes

static __device__ float4 g_pts4[NBATCH * NPTS];          // (x,y,z,|p|^2) by original idx
static __device__ float4 g_w3t4[64 * 32];                // [c][lane] -> outputs o=lane+32k
static __device__ int    g_hist[NBATCH * NSLAB][NCELL];
static __device__ int    g_cellstart[NBATCH * NSLAB][NCELL + 1];
static __device__ int    g_cursor[NBATCH * NSLAB][NCELL];
static __device__ float4 g_sp[(size_t)NBATCH * NSLAB * SLABPTS];  // binned points
static __device__ int    g_si[(size_t)NBATCH * NSLAB * SLABPTS];  // batch-local original idx
static __device__ int    g_lists[NBATCH * NQ * 96];      // [l1(32)|l2(64)]

__device__ __forceinline__ float sq3_rn(float x, float y, float z) {
    return __fadd_rn(__fadd_rn(__fmul_rn(x, x), __fmul_rn(y, y)), __fmul_rn(z, z));
}

__device__ __forceinline__ int query_flat_index(int q, int& b) {
    b = q >> 10;
    const int m = q & 1023;
    return (4 + 8 * (m >> 5)) * 256 + (4 + 8 * (m & 31));
}

__device__ __forceinline__ void radii(float& r1sq, float& r2sq) {
    r1sq = __fmul_rn(0.1f, 0.1f);
    r2sq = __fmul_rn(0.2f, 0.2f);
}

// d2 with the exact rounding order of the reference.
__device__ __forceinline__ float dist2_rn(float4 pt, float4 qp) {
    const float dot = __fadd_rn(__fadd_rn(__fmul_rn(pt.x, qp.x), __fmul_rn(pt.y, qp.y)),
                                __fmul_rn(pt.z, qp.z));
    return __fadd_rn(__fadd_rn(qp.w, pt.w), __fmul_rn(-2.0f, dot));
}

__device__ __forceinline__ int cell_of(float x, float y, float z) {
    const int cx = min(9, (int)(x * 10.0f));
    const int cy = min(9, (int)(y * 10.0f));
    const int cz = min(9, (int)(z * 10.0f));
    return (cz * 10 + cy) * 10 + cx;
}

// ---------------------------------------------------------------------------
// Kernel 0: pack pts; histogram cells per (batch, index-slab); pack w3.
// ---------------------------------------------------------------------------
__global__ __launch_bounds__(256) void prep_kernel(const float* __restrict__ pts,
                                                   const float* __restrict__ w3) {
    const int blk = blockIdx.x;
    if (blk < NBATCH * NPTS / 256) {
        const int i = blk * 256 + threadIdx.x;   // 0..131071
        const float x = __ldg(pts + 3 * i + 0);
        const float y = __ldg(pts + 3 * i + 1);
        const float z = __ldg(pts + 3 * i + 2);
        g_pts4[i] = make_float4(x, y, z, sq3_rn(x, y, z));
        const int b = i >> 16, pi = i & (NPTS - 1);
        atomicAdd(&g_hist[b * NSLAB + (pi >> 14)][cell_of(x, y, z)], 1);
    } else {
        const int i = (blk - NBATCH * NPTS / 256) * 256 + threadIdx.x;
        if (i < 64 * 32) {
            const int c = i >> 5, j = i & 31;
            g_w3t4[i] = make_float4(__ldg(w3 + (j +  0) * 64 + c),
                                    __ldg(w3 + (j + 32) * 64 + c),
                                    __ldg(w3 + (j + 64) * 64 + c),
                                    __ldg(w3 + (j + 96) * 64 + c));
        }
    }
}

// ---------------------------------------------------------------------------
// Kernel 1: exclusive scan of per-slab histograms.
// ---------------------------------------------------------------------------
__global__ __launch_bounds__(1024) void scan_kernel() {
    __shared__ int buf[2][1024];
    const int br = blockIdx.x, tid = threadIdx.x;
    int v = (tid < NCELL) ? g_hist[br][tid] : 0;
    buf[0][tid] = v;
    __syncthreads();
    int src = 0;
    for (int d = 1; d < 1024; d <<= 1) {
        int t = buf[src][tid];
        if (tid >= d) t += buf[src][tid - d];
        __syncthreads();
        buf[src ^ 1][tid] = t;
        src ^= 1;
        __syncthreads();
    }
    const int excl = (tid == 0) ? 0 : buf[src][tid - 1];
    if (tid <= NCELL) g_cellstart[br][tid] = excl;
    if (tid < NCELL)  g_cursor[br][tid] = excl;
}

// ---------------------------------------------------------------------------
// Kernel 2: scatter points into binned slabs.
// ---------------------------------------------------------------------------
__global__ __launch_bounds__(256) void scatter_kernel() {
    const int i = blockIdx.x * 256 + threadIdx.x;   // 0..131071
    const int b = i >> 16, pi = i & (NPTS - 1);
    const float4 p = g_pts4[i];
    const int br = b * NSLAB + (pi >> 14);
    const int pos = atomicAdd(&g_cursor[br][cell_of(p.x, p.y, p.z)], 1);
    g_sp[(size_t)br * SLABPTS + pos] = p;
    g_si[(size_t)br * SLABPTS + pos] = pi;
}

// ---------------------------------------------------------------------------
// Append first-K set bits (ascending) from nwords mask words starting at cnt0.
// Warp-collective, early exit per 32-word chunk. Returns total count seen.
// (R13 verbatim — known good.)
// ---------------------------------------------------------------------------
__device__ __forceinline__ int extract_append(
    const unsigned* __restrict__ mask, int nwords, int K, int lane,
    int* __restrict__ list, int cnt0, int idx_base)
{
    int cnt = cnt0;
    for (int w0 = 0; w0 < nwords && cnt < K; w0 += 32) {
        const unsigned v = mask[w0 + lane];
        const int pc = __popc(v);
        int pre = pc;
#pragma unroll
        for (int d = 1; d < 32; d <<= 1) {
            const int t = __shfl_up_sync(0xffffffffu, pre, d);
            if (lane >= d) pre += t;
        }
        int p = cnt + (pre - pc);
        unsigned vv = v;
        while (vv && p < K) {
            const int bit = __ffs(vv) - 1;
            list[p] = idx_base + (w0 + lane) * 32 + bit;
            p++; vv &= vv - 1;
        }
        cnt += __shfl_sync(0xffffffffu, pre, 31);
    }
    return cnt;
}

// ---------------------------------------------------------------------------
// Sphere-trimmed candidate loop over one slab; 2 warps split rows.
// Explicit cz/cy loops (no integer divides); per-cz dz2 hoisted.
// Sets bits (pi & 16383) in the shared per-query masks.
// ---------------------------------------------------------------------------
__device__ __forceinline__ void build_slab(
    int br, float4 qp, float r1sq, float r2sq,
    int wid, int lane, unsigned* __restrict__ m1, unsigned* __restrict__ m2)
{
    const float4* __restrict__ sp = g_sp + (size_t)br * SLABPTS;
    const int*    __restrict__ si = g_si + (size_t)br * SLABPTS;
    const int*    __restrict__ cs = g_cellstart[br];

    const int cy0 = max(0, (int)((qp.y - RP) * 10.0f));
    const int cy1 = min(9, (int)((qp.y + RP) * 10.0f));
    const int cz0 = max(0, (int)((qp.z - RP) * 10.0f));
    const int cz1 = min(9, (int)((qp.z + RP) * 10.0f));

    int rowidx = 0;
    for (int cz = cz0; cz <= cz1; cz++) {
        const float dz = fmaxf(0.0f, fmaxf(cz * 0.1f - qp.z, qp.z - (cz + 1) * 0.1f));
        const float dz2 = dz * dz;
        for (int cy = cy0; cy <= cy1; cy++) {
            const int mine = rowidx & 1;     // alternate rows between the 2 warps
            rowidx++;
            if (mine != wid) continue;
            const float dy = fmaxf(0.0f, fmaxf(cy * 0.1f - qp.y, qp.y - (cy + 1) * 0.1f));
            const float dyz2 = dz2 + dy * dy;
            if (dyz2 > r2sq + 1e-4f) continue;             // row outside ball
            const float w = sqrtf(fmaxf(r2sq - dyz2, 0.0f)) + 2e-3f;  // conservative
            const int cx0 = max(0, (int)((qp.x - w) * 10.0f));
            const int cx1 = min(9, (int)((qp.x + w) * 10.0f));
            const int row = (cz * 10 + cy) * 10;
            const int s = cs[row + cx0];
            const int e = cs[row + cx1 + 1];               // x-cells contiguous
            for (int j = s + lane; j < e; j += 32) {
                const float4 pt = __ldg(sp + j);
                const float d2 = dist2_rn(pt, qp);
                if (d2 < r2sq) {
                    const int bp = __ldg(si + j) & (SLABPTS - 1);
                    atomicOr(&m2[bp >> 5], 1u << (bp & 31));
                    if (d2 < r1sq) atomicOr(&m1[bp >> 5], 1u << (bp & 31));
                }
            }
        }
    }
}

// ---------------------------------------------------------------------------
// Kernel 3: ball query (R13 structure). Block = 64 threads = 1 query (2 warps).
// Slab loop with early exit; warps split build rows, then extract m1/m2 in
// parallel; already-full lists skip extraction (warp-uniform guard).
// ---------------------------------------------------------------------------
__global__ __launch_bounds__(64) void ballquery_kernel() {
    __shared__ unsigned m1[NW], m2[NW];    // 4 KB
    __shared__ int sl1[NS1], sl2[NS2], scnt[2];

    const int tid = threadIdx.x, lane = tid & 31, wid = tid >> 5;
    const int q = blockIdx.x, b = q >> 10;
    int bb;
    const int fi = query_flat_index(q, bb);
    const float4 qp = __ldg(g_pts4 + (size_t)b * NPTS + fi);
    float r1sq, r2sq; radii(r1sq, r2sq);

    int c1 = 0, c2 = 0;
    for (int s = 0; s < NSLAB; s++) {
        for (int i = tid; i < NW; i += 64) { m1[i] = 0u; m2[i] = 0u; }
        __syncthreads();
        build_slab(b * NSLAB + s, qp, r1sq, r2sq, wid, lane, m1, m2);
        __syncthreads();
        if (wid == 0) {
            int t = c1;
            if (c1 < NS1) t = extract_append(m1, NW, NS1, lane, sl1, c1, s * SLABPTS);
            if (lane == 0) scnt[0] = t;
        } else {
            int t = c2;
            if (c2 < NS2) t = extract_append(m2, NW, NS2, lane, sl2, c2, s * SLABPTS);
            if (lane == 0) scnt[1] = t;
        }
        __syncthreads();
        c1 = scnt[0]; c2 = scnt[1];
        if (c1 >= NS1 && c2 >= NS2) break;
    }

    // Padded write (reference: invalid -> first element, or 0 if none).
    if (wid == 0) {
        int* g1 = g_lists + q * 96;
        const int n1 = min(c1, NS1);
        const int f1 = (n1 > 0) ? sl1[0] : 0;
        g1[lane] = (lane < n1) ? sl1[lane] : f1;
    } else {
        int* g2 = g_lists + q * 96 + NS1;
        const int n2 = min(c2, NS2);
        const int f2 = (n2 > 0) ? sl2[0] : 0;
#pragma unroll
        for (int j = 0; j < 2; j++) {
            const int i = lane + j * 32;
            g2[i] = (i < n2) ? sl2[i] : f2;
        }
    }
}

// ---------------------------------------------------------------------------
// Kernel 4: MLP (R13 version — w3 pre-packed, no smem transpose preamble).
// ---------------------------------------------------------------------------
#define INVC 0.9999950000374997f

__device__ __forceinline__ void mlp_point(
    float gx, float gy, float gz, float qx, float qy, float qz,
    const float* __restrict__ sA, const float* __restrict__ scA, const float* __restrict__ biA,
    const float* __restrict__ sB, const float* __restrict__ scB, const float* __restrict__ biB,
    float f[32])
{
    const float x0 = gx - qx, x1 = gy - qy, x2 = gz - qz;
    float a[16];
#pragma unroll
    for (int o = 0; o < 16; o++) {
        const float* w = sA + o * 6;
        float y = x0 * w[0];
        y = fmaf(x1, w[1], y);
        y = fmaf(x2, w[2], y);
        y = fmaf(gx, w[3], y);
        y = fmaf(gy, w[4], y);
        y = fmaf(gz, w[5], y);
        a[o] = fmaxf(fmaf(y, scA[o], biA[o]), 0.0f);
    }
#pragma unroll
    for (int o = 0; o < 32; o++) {
        const float* w = sB + o * 16;
        float y = 0.0f;
#pragma unroll
        for (int c = 0; c < 16; c++) y = fmaf(a[c], w[c], y);
        f[o] = fmaxf(f[o], fmaxf(fmaf(y, scB[o], biB[o]), 0.0f));
    }
}

__device__ __forceinline__ void warp_max32(float f[32]) {
#pragma unroll
    for (int o = 0; o < 32; o++) {
        float v = f[o];
        v = fmaxf(v, __shfl_xor_sync(0xffffffffu, v, 16));
        v = fmaxf(v, __shfl_xor_sync(0xffffffffu, v, 8));
        v = fmaxf(v, __shfl_xor_sync(0xffffffffu, v, 4));
        v = fmaxf(v, __shfl_xor_sync(0xffffffffu, v, 2));
        v = fmaxf(v, __shfl_xor_sync(0xffffffffu, v, 1));
        f[o] = v;
    }
}

__global__ __launch_bounds__(256) void mlp_kernel(
    const float* __restrict__ w1a, const float* __restrict__ g1a, const float* __restrict__ b1a,
    const float* __restrict__ w1b, const float* __restrict__ g1b, const float* __restrict__ b1b,
    const float* __restrict__ w2a, const float* __restrict__ g2a, const float* __restrict__ b2a,
    const float* __restrict__ w2b, const float* __restrict__ g2b, const float* __restrict__ b2b,
    const float* __restrict__ b3,
    float* __restrict__ out)
{
    __shared__ float s_w1a[96],  s_w2a[96];
    __shared__ float s_w1b[512], s_w2b[512];
    __shared__ float s_sc1a[16], s_bi1a[16], s_sc2a[16], s_bi2a[16];
    __shared__ float s_sc1b[32], s_bi1b[32], s_sc2b[32], s_bi2b[32];

    const int tid = threadIdx.x;
    for (int i = tid; i < 96; i += 256)  { s_w1a[i] = w1a[i]; s_w2a[i] = w2a[i]; }
    for (int i = tid; i < 512; i += 256) { s_w1b[i] = w1b[i]; s_w2b[i] = w2b[i]; }
    if (tid < 16) {
        s_sc1a[tid] = g1a[tid] * INVC; s_bi1a[tid] = b1a[tid];
        s_sc2a[tid] = g2a[tid] * INVC; s_bi2a[tid] = b2a[tid];
    } else if (tid < 48) {
        const int i = tid - 16;
        s_sc1b[i] = g1b[i] * INVC; s_bi1b[i] = b1b[i];
        s_sc2b[i] = g2b[i] * INVC; s_bi2b[i] = b2b[i];
    }
    __syncthreads();

    const int lane = tid & 31;
    const int wid  = tid >> 5;
    const int q    = blockIdx.x * 8 + wid;
    int b;
    const int fi = query_flat_index(q, b);

    const float4* __restrict__ P4 = g_pts4 + (size_t)b * NPTS;
    const float4 qp = __ldg(P4 + fi);
    const float qx = qp.x, qy = qp.y, qz = qp.z;

    const int* lst = g_lists + q * 96;
    const int i0 = __ldg(lst + lane);
    const int i1 = __ldg(lst + NS1 + lane);
    const int i2 = __ldg(lst + NS1 + 32 + lane);
    const float4 n0 = __ldg(P4 + i0);
    const float4 n1 = __ldg(P4 + i1);
    const float4 n2 = __ldg(P4 + i2);

    float acc0 = __ldg(b3 + lane +  0);
    float acc1 = __ldg(b3 + lane + 32);
    float acc2 = __ldg(b3 + lane + 64);
    float acc3 = __ldg(b3 + lane + 96);

    {   // branch 1 (S=32)
        float f[32];
#pragma unroll
        for (int o = 0; o < 32; o++) f[o] = 0.0f;
        mlp_point(n0.x, n0.y, n0.z, qx, qy, qz, s_w1a, s_sc1a, s_bi1a, s_w1b, s_sc1b, s_bi1b, f);
        warp_max32(f);
#pragma unroll
        for (int c = 0; c < 32; c++) {
            const float4 w = __ldg(g_w3t4 + c * 32 + lane);
            acc0 = fmaf(f[c], w.x, acc0);
            acc1 = fmaf(f[c], w.y, acc1);
            acc2 = fmaf(f[c], w.z, acc2);
            acc3 = fmaf(f[c], w.w, acc3);
        }
    }
    {   // branch 2 (S=64)
        float f[32];
#pragma unroll
        for (int o = 0; o < 32; o++) f[o] = 0.0f;
        mlp_point(n1.x, n1.y, n1.z, qx, qy, qz, s_w2a, s_sc2a, s_bi2a, s_w2b, s_sc2b, s_bi2b, f);
        mlp_point(n2.x, n2.y, n2.z, qx, qy, qz, s_w2a, s_sc2a, s_bi2a, s_w2b, s_sc2b, s_bi2b, f);
        warp_max32(f);
#pragma unroll
        for (int c = 0; c < 32; c++) {
            const float4 w = __ldg(g_w3t4 + (c + 32) * 32 + lane);
            acc0 = fmaf(f[c], w.x, acc0);
            acc1 = fmaf(f[c], w.y, acc1);
            acc2 = fmaf(f[c], w.z, acc2);
            acc3 = fmaf(f[c], w.w, acc3);
        }
    }
    const size_t ob = (size_t)q * NOUT;
    out[ob + lane +  0] = acc0;
    out[ob + lane + 32] = acc1;
    out[ob + lane + 64] = acc2;
    out[ob + lane + 96] = acc3;
}

extern "C" void kernel_launch(void* const* d_in, const int* in_sizes, int n_in,
                              void* d_out, int out_size) {
    const float* pts = (const float*)d_in[0];
    const float* w1a = (const float*)d_in[1];
    const float* g1a = (const float*)d_in[2];
    const float* b1a = (const float*)d_in[3];
    const float* w1b = (const float*)d_in[4];
    const float* g1b = (const float*)d_in[5];
    const float* b1b = (const float*)d_in[6];
    const float* w2a = (const float*)d_in[7];
    const float* g2a = (const float*)d_in[8];
    const float* b2a = (const float*)d_in[9];
    const float* w2b = (const float*)d_in[10];
    const float* g2b = (const float*)d_in[11];
    const float* b2b = (const float*)d_in[12];
    const float* w3  = (const float*)d_in[13];
    const float* b3  = (const float*)d_in[14];
    float* out = (float*)d_out;

    static void* hist_ptr = nullptr;
    if (!hist_ptr) cudaGetSymbolAddress(&hist_ptr, g_hist);

    cudaMemsetAsync(hist_ptr, 0, sizeof(int) * NBATCH * NSLAB * NCELL);
    prep_kernel<<<NBATCH * NPTS / 256 + 8, 256>>>(pts, w3);
    scan_kernel<<<NBATCH * NSLAB, 1024>>>();
    scatter_kernel<<<NBATCH * NPTS / 256, 256>>>();
    ballquery_kernel<<<NBATCH * NQ, 64>>>();
    mlp_kernel<<<NBATCH * NQ / 8, 256>>>(w1a, g1a, b1a, w1b, g1b, b1b,
                                         w2a, g2a, b2a, w2b, g2b, b2b, b3, out);
}